// round 14
// baseline (speedup 1.0000x reference)
#include <cuda_runtime.h>
#include <cuda_fp16.h>
#include <math.h>
#include <cstdint>

#define NB 16
#define NN 2048
#define ND 128
#define NTH 128
#define LOG2E 1.4426950408889634f
#define QSCALE (0.08838834764831843f * 1.4426950408889634f)   // 1/sqrt(D) * log2(e)
#define ESHIFT 3.0f

// ---------------- device scratch ----------------
__device__ float g_bias[(size_t)NN * NN];   // (sum of biases)*log2e - ESHIFT*log2e
__device__ __align__(16) __half g_qh[(size_t)NB * NN * ND];
__device__ __align__(16) __half g_kh[(size_t)NB * NN * ND];
__device__ __align__(16) __half g_vh[(size_t)NB * NN * ND];

// ---------------- smem layout (bytes) ----------------
// KV ring: 2 stages x (Kh 16K | Vh 16K) = 64KB/CTA. Q staged through slot 1 K-area.
#define KV_STAGE 32768
#define T_KH 0
#define T_VH 16384
#define SMEM_TOTAL 65536

// ---------------- PTX helpers ----------------
__device__ __forceinline__ uint32_t smem_u32(const void* p) {
    uint32_t a;
    asm("{ .reg .u64 t; cvta.to.shared.u64 t, %1; cvt.u32.u64 %0, t; }" : "=r"(a) : "l"(p));
    return a;
}
__device__ __forceinline__ void cpa16(uint32_t dst, const void* src) {
    asm volatile("cp.async.cg.shared.global [%0], [%1], 16;" :: "r"(dst), "l"(src));
}
#define CP_COMMIT() asm volatile("cp.async.commit_group;" ::: "memory")
#define CP_WAIT0()  asm volatile("cp.async.wait_group 0;" ::: "memory")

__device__ __forceinline__ void ldsm4(uint32_t& r0, uint32_t& r1, uint32_t& r2, uint32_t& r3,
                                      uint32_t addr) {
    asm volatile("ldmatrix.sync.aligned.m8n8.x4.shared.b16 {%0,%1,%2,%3}, [%4];"
                 : "=r"(r0), "=r"(r1), "=r"(r2), "=r"(r3) : "r"(addr));
}
__device__ __forceinline__ void ldsm4t(uint32_t& r0, uint32_t& r1, uint32_t& r2, uint32_t& r3,
                                       uint32_t addr) {
    asm volatile("ldmatrix.sync.aligned.m8n8.x4.trans.shared.b16 {%0,%1,%2,%3}, [%4];"
                 : "=r"(r0), "=r"(r1), "=r"(r2), "=r"(r3) : "r"(addr));
}
__device__ __forceinline__ void mma_f16(float* d, const uint32_t* a, uint32_t b0, uint32_t b1) {
    asm volatile(
        "mma.sync.aligned.m16n8k16.row.col.f32.f16.f16.f32 "
        "{%0,%1,%2,%3}, {%4,%5,%6,%7}, {%8,%9}, {%0,%1,%2,%3};"
        : "+f"(d[0]), "+f"(d[1]), "+f"(d[2]), "+f"(d[3])
        : "r"(a[0]), "r"(a[1]), "r"(a[2]), "r"(a[3]), "r"(b0), "r"(b1));
}
__device__ __forceinline__ uint32_t h2u(__half2 h) { return *(uint32_t*)&h; }
__device__ __forceinline__ float ex2f(float x) {
    float y; asm("ex2.approx.ftz.f32 %0, %1;" : "=f"(y) : "f"(x)); return y;
}

// ---------------- fused prep kernel ----------------
#define BIAS_BLKS 1024
#define QKV_BLKS  2048

__global__ void prep_all(const float4* __restrict__ Q, const float4* __restrict__ K,
                         const float4* __restrict__ V,
                         const float4* __restrict__ ba, const float4* __restrict__ bb,
                         const float4* __restrict__ bc, const float4* __restrict__ bd,
                         const void* __restrict__ im_raw, const void* __restrict__ em_raw) {
    const int blk = blockIdx.x;
    if (blk < BIAS_BLKS) {
        const int n4 = (NN * NN) / 4;
        float4* out = (float4*)g_bias;
        const float sh = ESHIFT * LOG2E;
        for (int i = blk * blockDim.x + threadIdx.x; i < n4; i += BIAS_BLKS * blockDim.x) {
            float4 x = ba[i], y = bb[i], z = bc[i], w = bd[i];
            float4 r;
            r.x = (x.x + y.x + z.x + w.x) * LOG2E - sh;
            r.y = (x.y + y.y + z.y + w.y) * LOG2E - sh;
            r.z = (x.z + y.z + z.z + w.z) * LOG2E - sh;
            r.w = (x.w + y.w + z.w + w.w) * LOG2E - sh;
            out[i] = r;
        }
        return;
    }
    __shared__ int mode_i, mode_e;
    if (threadIdx.x == 0) {
        const unsigned int* wi = (const unsigned int*)im_raw;
        const unsigned int* we = (const unsigned int*)em_raw;
        int mi = 0, me = 0;
        for (int k = 0; k < 64; k++) {
            unsigned int a = wi[k], b = we[k];
            if (a == 0x3F800000u) mi = 2; else if (mi != 2 && a > 1u) mi = 1;
            if (b == 0x3F800000u) me = 2; else if (me != 2 && b > 1u) me = 1;
        }
        mode_i = mi; mode_e = me;
    }
    __syncthreads();
    const int mi = mode_i, me = mode_e;

    const int n4 = NB * NN * ND / 4;
    uint2* qh = (uint2*)g_qh;
    uint2* kh = (uint2*)g_kh;
    uint2* vh = (uint2*)g_vh;
    for (int i = (blk - BIAS_BLKS) * blockDim.x + threadIdx.x; i < n4;
         i += QKV_BLKS * blockDim.x) {
        const int bn = i >> 5;
        bool kb, qb;
        if (mi == 1)      kb = (((const unsigned char*)im_raw)[bn] != 0);
        else if (mi == 2) kb = (((const float*)im_raw)[bn] != 0.0f);
        else              kb = (((const int*)im_raw)[bn] != 0);
        if (me == 1)      qb = (((const unsigned char*)em_raw)[bn] != 0);
        else if (me == 2) qb = (((const float*)em_raw)[bn] != 0.0f);
        else              qb = (((const int*)em_raw)[bn] != 0);
        const float qmf = qb ? QSCALE : 0.0f;
        const float kmf = kb ? 1.0f : 0.0f;

        float4 q = Q[i];
        __half2 q01 = __floats2half2_rn(q.x * qmf, q.y * qmf);
        __half2 q23 = __floats2half2_rn(q.z * qmf, q.w * qmf);
        qh[i] = make_uint2(h2u(q01), h2u(q23));

        float4 k = K[i];
        __half2 kh01 = __floats2half2_rn(k.x * kmf, k.y * kmf);
        __half2 kh23 = __floats2half2_rn(k.z * kmf, k.w * kmf);
        kh[i] = make_uint2(h2u(kh01), h2u(kh23));

        float4 v = V[i];
        __half2 vh01 = __floats2half2_rn(v.x * kmf, v.y * kmf);
        __half2 vh23 = __floats2half2_rn(v.z * kmf, v.w * kmf);
        vh[i] = make_uint2(h2u(vh01), h2u(vh23));
    }
}

// ---------------- KV stage loader: Kh|Vh, 64 rows x 256B each, swizzled ----------------
__device__ __forceinline__ void load_kv(uint32_t stage_base, int b, int k0, int tid) {
    const size_t gbyte = ((size_t)b * NN + k0) * ND * 2;
    const char* sk_h = (const char*)g_kh + gbyte;
    const char* sv_h = (const char*)g_vh + gbyte;
#pragma unroll
    for (int j = 0; j < 8; j++) {
        int idx = tid + NTH * j;
        int row = idx >> 4, c = idx & 15;
        uint32_t d = row * 256 + ((c ^ (row & 7)) << 4);
        uint32_t s = row * 256 + c * 16;
        cpa16(stage_base + T_KH + d, sk_h + s);
        cpa16(stage_base + T_VH + d, sv_h + s);
    }
}

// ---------------- FA2-style kernel: 4 warps x 16 q-rows (64-row tile), 3 CTA/SM ----------------
__global__ __launch_bounds__(NTH, 3)
void attn_mma(float* __restrict__ Og) {
    extern __shared__ char smc[];
    const uint32_t base = smem_u32(smc);
    const int tid = threadIdx.x;
    const int lane = tid & 31, wid = tid >> 5;
    const int g = lane >> 2, r = lane & 3;
    const int lane7 = lane & 7, laneHi = lane >> 4, lane8 = (lane >> 3) & 1;
    const int b = blockIdx.y;
    const int qt = (int)gridDim.x - 1 - (int)blockIdx.x;
    const int q0 = qt * 64;
    const int nkt = qt + 1;

    // ---- prologue: one group = KV stage 0 (slot 0) + Q staged into slot 1 K-area ----
    load_kv(base, b, 0, tid);
    {
        const char* srcq = (const char*)g_qh + ((size_t)b * NN + q0) * ND * 2;
#pragma unroll
        for (int j = 0; j < 8; j++) {
            int idx = tid + NTH * j;
            int row = idx >> 4, c = idx & 15;
            cpa16(base + KV_STAGE + row * 256 + ((c ^ (row & 7)) << 4),
                  srcq + row * 256 + c * 16);
        }
    }
    CP_COMMIT();
    CP_WAIT0();
    __syncthreads();

    // ---- load Q fragments once: 16 rows x 128 k, persistent in registers ----
    uint32_t qf[8][4];
    {
        const uint32_t qrow = base + KV_STAGE + (uint32_t)(16 * wid + (lane & 15)) * 256;
#pragma unroll
        for (int ks = 0; ks < 8; ks++) {
            const uint32_t qoff = (uint32_t)(((laneHi + 2 * ks) ^ lane7) << 4);
            ldsm4(qf[ks][0], qf[ks][1], qf[ks][2], qf[ks][3], qrow + qoff);
        }
    }
    __syncthreads();   // all warps done reading Q before slot 1 is prefetched over

    // ---- per-lane address precompute ----
    uint32_t krowb[4];
#pragma unroll
    for (int t = 0; t < 4; t++)
        krowb[t] = (uint32_t)(16 * t + 8 * laneHi + lane7) * 256;
    const uint32_t vrow256 = (uint32_t)(lane7 + 8 * lane8) * 256;
    uint32_t cvx[8];
#pragma unroll
    for (int p = 0; p < 8; p++)
        cvx[p] = (uint32_t)(((2 * p + laneHi) ^ lane7) << 4);

    const int row0g = q0 + 16 * wid + g;                  // this thread's first q-row
    const char* bp = (const char*)g_bias + (((size_t)row0g * NN) + 2 * r) * 4;

    float o_acc[16][4];
#pragma unroll
    for (int dt = 0; dt < 16; dt++)
#pragma unroll
        for (int i = 0; i < 4; i++) o_acc[dt][i] = 0.0f;
    float lsum0 = 0.0f, lsum1 = 0.0f;

    for (int kt = 0; kt < nkt; kt++) {
        const int k0 = kt * 64;
        const uint32_t kvb = base + (uint32_t)(kt & 1) * KV_STAGE;

        // ---- distance-1 prefetch: stage kt+1 into the other slot (L2-resident src) ----
        if (kt + 1 < nkt) {
            load_kv(base + (uint32_t)((kt + 1) & 1) * KV_STAGE, b, k0 + 64, tid);
            CP_COMMIT();
        }

        // ---- bias: local offsets only (bp carries the k0 advance) ----
        float2 bias2[8][2];
#pragma unroll
        for (int nt = 0; nt < 8; nt++) {
#pragma unroll
            for (int h = 0; h < 2; h++)
                bias2[nt][h] = __ldg((const float2*)(bp +
                    ((size_t)(8 * h) * NN + (size_t)(8 * nt)) * 4));
        }

        // ---- QK: S(16x64) = Q(16x128) x K^T; K streamed per-t (min liveness) ----
        float s[8][4];
#pragma unroll
        for (int nt = 0; nt < 8; nt++)
#pragma unroll
            for (int i = 0; i < 4; i++) s[nt][i] = 0.0f;

#pragma unroll
        for (int ks = 0; ks < 8; ks++) {
            const uint32_t koff = (uint32_t)(((lane8 + 2 * ks) ^ lane7) << 4);
#pragma unroll
            for (int t = 0; t < 4; t++) {
                uint32_t k0r, k1r, k2r, k3r;
                ldsm4(k0r, k1r, k2r, k3r, kvb + T_KH + krowb[t] + koff);
                mma_f16(s[2 * t],     qf[ks], k0r, k1r);
                mma_f16(s[2 * t + 1], qf[ks], k2r, k3r);
            }
        }

        // ---- chunked softmax + PV: chunk c = score cols 16c..16c+15 ----
        const bool safe = (k0 + 63 <= q0);
#pragma unroll
        for (int c = 0; c < 4; c++) {
            uint32_t pf[4];
#pragma unroll
            for (int j = 0; j < 2; j++) {
                const int nt = 2 * c + j;
                float p0 = ex2f(s[nt][0] + bias2[nt][0].x);
                float p1 = ex2f(s[nt][1] + bias2[nt][0].y);
                float p2 = ex2f(s[nt][2] + bias2[nt][1].x);
                float p3 = ex2f(s[nt][3] + bias2[nt][1].y);
                if (!safe) {
                    const int colg = k0 + 8 * nt + 2 * r;
                    p0 = (colg     <= row0g)     ? p0 : 0.0f;
                    p1 = (colg + 1 <= row0g)     ? p1 : 0.0f;
                    p2 = (colg     <= row0g + 8) ? p2 : 0.0f;
                    p3 = (colg + 1 <= row0g + 8) ? p3 : 0.0f;
                }
                lsum0 += p0 + p1;
                lsum1 += p2 + p3;
                pf[2 * j]     = h2u(__floats2half2_rn(p0, p1));
                pf[2 * j + 1] = h2u(__floats2half2_rn(p2, p3));
            }
            // PV for this chunk: V streamed per-p (min liveness)
            const uint32_t vbase = kvb + T_VH + vrow256 + (uint32_t)c * 4096;
#pragma unroll
            for (int p = 0; p < 8; p++) {
                uint32_t v0, v1, v2, v3;
                ldsm4t(v0, v1, v2, v3, vbase + cvx[p]);
                mma_f16(o_acc[2 * p],     pf, v0, v1);
                mma_f16(o_acc[2 * p + 1], pf, v2, v3);
            }
        }

        // ---- end of iter: stage kt+1 must be complete; publish slot reuse ----
        if (kt + 1 < nkt) {
            CP_WAIT0();
            __syncthreads();
        }
        bp += 256;
    }

    // ---- epilogue: quad-reduce l (warp-local rows), normalize, write ----
    lsum0 += __shfl_xor_sync(0xffffffffu, lsum0, 1);
    lsum0 += __shfl_xor_sync(0xffffffffu, lsum0, 2);
    lsum1 += __shfl_xor_sync(0xffffffffu, lsum1, 1);
    lsum1 += __shfl_xor_sync(0xffffffffu, lsum1, 2);
    const float inv0 = 1.0f / lsum0;
    const float inv1 = 1.0f / lsum1;

    float* dst0 = Og + ((size_t)b * NN + row0g) * ND;
    float* dst1 = dst0 + 8 * ND;
#pragma unroll
    for (int dt = 0; dt < 16; dt++) {
        float2 v0, v1;
        v0.x = o_acc[dt][0] * inv0;
        v0.y = o_acc[dt][1] * inv0;
        v1.x = o_acc[dt][2] * inv1;
        v1.y = o_acc[dt][3] * inv1;
        *(float2*)(dst0 + 8 * dt + 2 * r) = v0;
        *(float2*)(dst1 + 8 * dt + 2 * r) = v1;
    }
}

// ---------------- launch ----------------
extern "C" void kernel_launch(void* const* d_in, const int* in_sizes, int n_in,
                              void* d_out, int out_size) {
    const float4* Q = (const float4*)d_in[0];
    const float4* K = (const float4*)d_in[1];
    const float4* V = (const float4*)d_in[2];
    const float4* b0 = (const float4*)d_in[3];
    const float4* b1 = (const float4*)d_in[4];
    const float4* b2 = (const float4*)d_in[5];
    const float4* b3 = (const float4*)d_in[6];
    const void* im = d_in[7];
    const void* em = d_in[8];
    float* O = (float*)d_out;

    prep_all<<<BIAS_BLKS + QKV_BLKS, 256>>>(Q, K, V, b0, b1, b2, b3, im, em);

    cudaFuncSetAttribute(attn_mma, cudaFuncAttributeMaxDynamicSharedMemorySize, SMEM_TOTAL);
    dim3 grid(NN / 64, NB);
    attn_mma<<<grid, NTH, SMEM_TOTAL>>>(O);
}

// round 15
// speedup vs baseline: 1.0201x; 1.0201x over previous
#include <cuda_runtime.h>
#include <cuda_fp16.h>
#include <math.h>
#include <cstdint>

#define NB 16
#define NN 2048
#define ND 128
#define NTH 128
#define LOG2E 1.4426950408889634f
#define QSCALE (0.08838834764831843f * 1.4426950408889634f)   // 1/sqrt(D) * log2(e)
#define ESHIFT 3.0f
#define SPLIT_ROW0 960          // rows >= this (qt >= 15) are 2-way split-K

// ---------------- device scratch ----------------
__device__ float g_bias[(size_t)NN * NN];   // (sum of biases)*log2e - ESHIFT*log2e
__device__ __align__(16) __half g_qh[(size_t)NB * NN * ND];
__device__ __align__(16) __half g_kh[(size_t)NB * NN * ND];
__device__ __align__(16) __half g_vh[(size_t)NB * NN * ND];
__device__ __align__(16) float g_p0[(size_t)NB * NN * ND];   // split-K partial O, part 0
__device__ __align__(16) float g_p1[(size_t)NB * NN * ND];   // part 1
__device__ float g_l0[NB * NN];
__device__ float g_l1[NB * NN];

// ---------------- smem layout (bytes) ----------------
#define KV_STAGE 32768
#define T_KH 0
#define T_VH 16384
#define SMEM_TOTAL 65536

// ---------------- PTX helpers ----------------
__device__ __forceinline__ uint32_t smem_u32(const void* p) {
    uint32_t a;
    asm("{ .reg .u64 t; cvta.to.shared.u64 t, %1; cvt.u32.u64 %0, t; }" : "=r"(a) : "l"(p));
    return a;
}
__device__ __forceinline__ void cpa16(uint32_t dst, const void* src) {
    asm volatile("cp.async.cg.shared.global [%0], [%1], 16;" :: "r"(dst), "l"(src));
}
#define CP_COMMIT() asm volatile("cp.async.commit_group;" ::: "memory")
#define CP_WAIT0()  asm volatile("cp.async.wait_group 0;" ::: "memory")

__device__ __forceinline__ void ldsm4(uint32_t& r0, uint32_t& r1, uint32_t& r2, uint32_t& r3,
                                      uint32_t addr) {
    asm volatile("ldmatrix.sync.aligned.m8n8.x4.shared.b16 {%0,%1,%2,%3}, [%4];"
                 : "=r"(r0), "=r"(r1), "=r"(r2), "=r"(r3) : "r"(addr));
}
__device__ __forceinline__ void ldsm4t(uint32_t& r0, uint32_t& r1, uint32_t& r2, uint32_t& r3,
                                       uint32_t addr) {
    asm volatile("ldmatrix.sync.aligned.m8n8.x4.trans.shared.b16 {%0,%1,%2,%3}, [%4];"
                 : "=r"(r0), "=r"(r1), "=r"(r2), "=r"(r3) : "r"(addr));
}
__device__ __forceinline__ void mma_f16(float* d, const uint32_t* a, uint32_t b0, uint32_t b1) {
    asm volatile(
        "mma.sync.aligned.m16n8k16.row.col.f32.f16.f16.f32 "
        "{%0,%1,%2,%3}, {%4,%5,%6,%7}, {%8,%9}, {%0,%1,%2,%3};"
        : "+f"(d[0]), "+f"(d[1]), "+f"(d[2]), "+f"(d[3])
        : "r"(a[0]), "r"(a[1]), "r"(a[2]), "r"(a[3]), "r"(b0), "r"(b1));
}
__device__ __forceinline__ uint32_t h2u(__half2 h) { return *(uint32_t*)&h; }
__device__ __forceinline__ float ex2f(float x) {
    float y; asm("ex2.approx.ftz.f32 %0, %1;" : "=f"(y) : "f"(x)); return y;
}

// ---------------- fused prep kernel ----------------
#define BIAS_BLKS 1024
#define QKV_BLKS  2048

__global__ void prep_all(const float4* __restrict__ Q, const float4* __restrict__ K,
                         const float4* __restrict__ V,
                         const float4* __restrict__ ba, const float4* __restrict__ bb,
                         const float4* __restrict__ bc, const float4* __restrict__ bd,
                         const void* __restrict__ im_raw, const void* __restrict__ em_raw) {
    const int blk = blockIdx.x;
    if (blk < BIAS_BLKS) {
        const int n4 = (NN * NN) / 4;
        float4* out = (float4*)g_bias;
        const float sh = ESHIFT * LOG2E;
        for (int i = blk * blockDim.x + threadIdx.x; i < n4; i += BIAS_BLKS * blockDim.x) {
            float4 x = ba[i], y = bb[i], z = bc[i], w = bd[i];
            float4 r;
            r.x = (x.x + y.x + z.x + w.x) * LOG2E - sh;
            r.y = (x.y + y.y + z.y + w.y) * LOG2E - sh;
            r.z = (x.z + y.z + z.z + w.z) * LOG2E - sh;
            r.w = (x.w + y.w + z.w + w.w) * LOG2E - sh;
            out[i] = r;
        }
        return;
    }
    __shared__ int mode_i, mode_e;
    if (threadIdx.x == 0) {
        const unsigned int* wi = (const unsigned int*)im_raw;
        const unsigned int* we = (const unsigned int*)em_raw;
        int mi = 0, me = 0;
        for (int k = 0; k < 64; k++) {
            unsigned int a = wi[k], b = we[k];
            if (a == 0x3F800000u) mi = 2; else if (mi != 2 && a > 1u) mi = 1;
            if (b == 0x3F800000u) me = 2; else if (me != 2 && b > 1u) me = 1;
        }
        mode_i = mi; mode_e = me;
    }
    __syncthreads();
    const int mi = mode_i, me = mode_e;

    const int n4 = NB * NN * ND / 4;
    uint2* qh = (uint2*)g_qh;
    uint2* kh = (uint2*)g_kh;
    uint2* vh = (uint2*)g_vh;
    for (int i = (blk - BIAS_BLKS) * blockDim.x + threadIdx.x; i < n4;
         i += QKV_BLKS * blockDim.x) {
        const int bn = i >> 5;
        bool kb, qb;
        if (mi == 1)      kb = (((const unsigned char*)im_raw)[bn] != 0);
        else if (mi == 2) kb = (((const float*)im_raw)[bn] != 0.0f);
        else              kb = (((const int*)im_raw)[bn] != 0);
        if (me == 1)      qb = (((const unsigned char*)em_raw)[bn] != 0);
        else if (me == 2) qb = (((const float*)em_raw)[bn] != 0.0f);
        else              qb = (((const int*)em_raw)[bn] != 0);
        const float qmf = qb ? QSCALE : 0.0f;
        const float kmf = kb ? 1.0f : 0.0f;

        float4 q = Q[i];
        __half2 q01 = __floats2half2_rn(q.x * qmf, q.y * qmf);
        __half2 q23 = __floats2half2_rn(q.z * qmf, q.w * qmf);
        qh[i] = make_uint2(h2u(q01), h2u(q23));

        float4 k = K[i];
        __half2 kh01 = __floats2half2_rn(k.x * kmf, k.y * kmf);
        __half2 kh23 = __floats2half2_rn(k.z * kmf, k.w * kmf);
        kh[i] = make_uint2(h2u(kh01), h2u(kh23));

        float4 v = V[i];
        __half2 vh01 = __floats2half2_rn(v.x * kmf, v.y * kmf);
        __half2 vh23 = __floats2half2_rn(v.z * kmf, v.w * kmf);
        vh[i] = make_uint2(h2u(vh01), h2u(vh23));
    }
}

// ---------------- combine kernel: O = (P0 + P1) / (l0 + l1) for split rows ----------------
__global__ void combine_split(float4* __restrict__ O) {
    const int total = NB * (NN - SPLIT_ROW0) * (ND / 4);
    int idx = blockIdx.x * blockDim.x + threadIdx.x;
    if (idx >= total) return;
    const int d4 = idx & 31;                       // ND/4 = 32
    const int rowc = (idx >> 5) % (NN - SPLIT_ROW0);
    const int b = idx / (32 * (NN - SPLIT_ROW0));
    const int row = SPLIT_ROW0 + rowc;
    const size_t off = ((size_t)b * NN + row) * (ND / 4) + d4;
    float4 a = ((const float4*)g_p0)[off];
    float4 c = ((const float4*)g_p1)[off];
    const float inv = 1.0f / (g_l0[b * NN + row] + g_l1[b * NN + row]);
    float4 o;
    o.x = (a.x + c.x) * inv;
    o.y = (a.y + c.y) * inv;
    o.z = (a.z + c.z) * inv;
    o.w = (a.w + c.w) * inv;
    O[off] = o;
}

// ---------------- KV stage loader: Kh|Vh, 64 rows x 256B each, swizzled ----------------
__device__ __forceinline__ void load_kv(uint32_t stage_base, int b, int k0, int tid) {
    const size_t gbyte = ((size_t)b * NN + k0) * ND * 2;
    const char* sk_h = (const char*)g_kh + gbyte;
    const char* sv_h = (const char*)g_vh + gbyte;
#pragma unroll
    for (int j = 0; j < 8; j++) {
        int idx = tid + NTH * j;
        int row = idx >> 4, c = idx & 15;
        uint32_t d = row * 256 + ((c ^ (row & 7)) << 4);
        uint32_t s = row * 256 + c * 16;
        cpa16(stage_base + T_KH + d, sk_h + s);
        cpa16(stage_base + T_VH + d, sv_h + s);
    }
}

// ---------------- FA2-style kernel with 2-way split-K on heavy q-tiles ----------------
__global__ __launch_bounds__(NTH, 3)
void attn_mma(float* __restrict__ Og) {
    extern __shared__ char smc[];
    const uint32_t base = smem_u32(smc);
    const int tid = threadIdx.x;
    const int lane = tid & 31, wid = tid >> 5;
    const int g = lane >> 2, r = lane & 3;
    const int lane7 = lane & 7, laneHi = lane >> 4, lane8 = (lane >> 3) & 1;
    const int b = blockIdx.y;

    // ---- piece decode: x<34 -> split halves of qt 31..15 (big first); else single ----
    const int x = blockIdx.x;
    int qt, kt0, kt1, part, split;
    if (x < 34) {
        qt = 31 - (x >> 1);
        part = x & 1;
        split = 1;
        const int nk = qt + 1, h = (nk + 1) >> 1;
        kt0 = part ? h : 0;
        kt1 = part ? nk : h;
    } else {
        qt = 48 - x;
        part = 0;
        split = 0;
        kt0 = 0;
        kt1 = qt + 1;
    }
    const int q0 = qt * 64;

    // ---- prologue: KV stage kt0 into slot kt0&1, Q staged into the other slot ----
    load_kv(base + (uint32_t)(kt0 & 1) * KV_STAGE, b, kt0 * 64, tid);
    {
        const uint32_t qslot = (uint32_t)((kt0 & 1) ^ 1) * KV_STAGE;
        const char* srcq = (const char*)g_qh + ((size_t)b * NN + q0) * ND * 2;
#pragma unroll
        for (int j = 0; j < 8; j++) {
            int idx = tid + NTH * j;
            int row = idx >> 4, c = idx & 15;
            cpa16(base + qslot + row * 256 + ((c ^ (row & 7)) << 4),
                  srcq + row * 256 + c * 16);
        }
    }
    CP_COMMIT();
    CP_WAIT0();
    __syncthreads();

    // ---- load Q fragments once: 16 rows x 128 k, persistent in registers ----
    uint32_t qf[8][4];
    {
        const uint32_t qrow = base + (uint32_t)((kt0 & 1) ^ 1) * KV_STAGE +
                              (uint32_t)(16 * wid + (lane & 15)) * 256;
#pragma unroll
        for (int ks = 0; ks < 8; ks++) {
            const uint32_t qoff = (uint32_t)(((laneHi + 2 * ks) ^ lane7) << 4);
            ldsm4(qf[ks][0], qf[ks][1], qf[ks][2], qf[ks][3], qrow + qoff);
        }
    }
    __syncthreads();   // Q reads done before the other slot is prefetched over

    // ---- per-lane address precompute ----
    uint32_t krowb[4];
#pragma unroll
    for (int t = 0; t < 4; t++)
        krowb[t] = (uint32_t)(16 * t + 8 * laneHi + lane7) * 256;
    const uint32_t vrow256 = (uint32_t)(lane7 + 8 * lane8) * 256;
    uint32_t cvx[8];
#pragma unroll
    for (int p = 0; p < 8; p++)
        cvx[p] = (uint32_t)(((2 * p + laneHi) ^ lane7) << 4);

    const int row0g = q0 + 16 * wid + g;
    const char* bp = (const char*)g_bias +
                     (((size_t)row0g * NN) + 2 * r + (size_t)kt0 * 64) * 4;

    float o_acc[16][4];
#pragma unroll
    for (int dt = 0; dt < 16; dt++)
#pragma unroll
        for (int i = 0; i < 4; i++) o_acc[dt][i] = 0.0f;
    float lsum0 = 0.0f, lsum1 = 0.0f;

    for (int kt = kt0; kt < kt1; kt++) {
        const int k0 = kt * 64;
        const uint32_t kvb = base + (uint32_t)(kt & 1) * KV_STAGE;

        // ---- distance-1 prefetch (src L2-resident) ----
        if (kt + 1 < kt1) {
            load_kv(base + (uint32_t)((kt + 1) & 1) * KV_STAGE, b, k0 + 64, tid);
            CP_COMMIT();
        }

        // ---- bias: local offsets only (bp carries the k0 advance) ----
        float2 bias2[8][2];
#pragma unroll
        for (int nt = 0; nt < 8; nt++) {
#pragma unroll
            for (int h = 0; h < 2; h++)
                bias2[nt][h] = __ldg((const float2*)(bp +
                    ((size_t)(8 * h) * NN + (size_t)(8 * nt)) * 4));
        }

        // ---- QK: S(16x64) = Q(16x128) x K^T; K streamed per-t ----
        float s[8][4];
#pragma unroll
        for (int nt = 0; nt < 8; nt++)
#pragma unroll
            for (int i = 0; i < 4; i++) s[nt][i] = 0.0f;

#pragma unroll
        for (int ks = 0; ks < 8; ks++) {
            const uint32_t koff = (uint32_t)(((lane8 + 2 * ks) ^ lane7) << 4);
#pragma unroll
            for (int t = 0; t < 4; t++) {
                uint32_t k0r, k1r, k2r, k3r;
                ldsm4(k0r, k1r, k2r, k3r, kvb + T_KH + krowb[t] + koff);
                mma_f16(s[2 * t],     qf[ks], k0r, k1r);
                mma_f16(s[2 * t + 1], qf[ks], k2r, k3r);
            }
        }

        // ---- chunked softmax + PV ----
        const bool safe = (k0 + 63 <= q0);
#pragma unroll
        for (int c = 0; c < 4; c++) {
            uint32_t pf[4];
#pragma unroll
            for (int j = 0; j < 2; j++) {
                const int nt = 2 * c + j;
                float p0 = ex2f(s[nt][0] + bias2[nt][0].x);
                float p1 = ex2f(s[nt][1] + bias2[nt][0].y);
                float p2 = ex2f(s[nt][2] + bias2[nt][1].x);
                float p3 = ex2f(s[nt][3] + bias2[nt][1].y);
                if (!safe) {
                    const int colg = k0 + 8 * nt + 2 * r;
                    p0 = (colg     <= row0g)     ? p0 : 0.0f;
                    p1 = (colg + 1 <= row0g)     ? p1 : 0.0f;
                    p2 = (colg     <= row0g + 8) ? p2 : 0.0f;
                    p3 = (colg + 1 <= row0g + 8) ? p3 : 0.0f;
                }
                lsum0 += p0 + p1;
                lsum1 += p2 + p3;
                pf[2 * j]     = h2u(__floats2half2_rn(p0, p1));
                pf[2 * j + 1] = h2u(__floats2half2_rn(p2, p3));
            }
            const uint32_t vbase = kvb + T_VH + vrow256 + (uint32_t)c * 4096;
#pragma unroll
            for (int p = 0; p < 8; p++) {
                uint32_t v0, v1, v2, v3;
                ldsm4t(v0, v1, v2, v3, vbase + cvx[p]);
                mma_f16(o_acc[2 * p],     pf, v0, v1);
                mma_f16(o_acc[2 * p + 1], pf, v2, v3);
            }
        }

        if (kt + 1 < kt1) {
            CP_WAIT0();
            __syncthreads();
        }
        bp += 256;
    }

    // ---- epilogue ----
    lsum0 += __shfl_xor_sync(0xffffffffu, lsum0, 1);
    lsum0 += __shfl_xor_sync(0xffffffffu, lsum0, 2);
    lsum1 += __shfl_xor_sync(0xffffffffu, lsum1, 1);
    lsum1 += __shfl_xor_sync(0xffffffffu, lsum1, 2);

    if (!split) {
        const float inv0 = 1.0f / lsum0;
        const float inv1 = 1.0f / lsum1;
        float* dst0 = Og + ((size_t)b * NN + row0g) * ND;
        float* dst1 = dst0 + 8 * ND;
#pragma unroll
        for (int dt = 0; dt < 16; dt++) {
            float2 v0, v1;
            v0.x = o_acc[dt][0] * inv0;
            v0.y = o_acc[dt][1] * inv0;
            v1.x = o_acc[dt][2] * inv1;
            v1.y = o_acc[dt][3] * inv1;
            *(float2*)(dst0 + 8 * dt + 2 * r) = v0;
            *(float2*)(dst1 + 8 * dt + 2 * r) = v1;
        }
    } else {
        float* gp = part ? g_p1 : g_p0;
        float* gl = part ? g_l1 : g_l0;
        float* dst0 = gp + ((size_t)b * NN + row0g) * ND;
        float* dst1 = dst0 + 8 * ND;
#pragma unroll
        for (int dt = 0; dt < 16; dt++) {
            *(float2*)(dst0 + 8 * dt + 2 * r) = make_float2(o_acc[dt][0], o_acc[dt][1]);
            *(float2*)(dst1 + 8 * dt + 2 * r) = make_float2(o_acc[dt][2], o_acc[dt][3]);
        }
        if (r == 0) {
            gl[b * NN + row0g] = lsum0;
            gl[b * NN + row0g + 8] = lsum1;
        }
    }
}

// ---------------- launch ----------------
extern "C" void kernel_launch(void* const* d_in, const int* in_sizes, int n_in,
                              void* d_out, int out_size) {
    const float4* Q = (const float4*)d_in[0];
    const float4* K = (const float4*)d_in[1];
    const float4* V = (const float4*)d_in[2];
    const float4* b0 = (const float4*)d_in[3];
    const float4* b1 = (const float4*)d_in[4];
    const float4* b2 = (const float4*)d_in[5];
    const float4* b3 = (const float4*)d_in[6];
    const void* im = d_in[7];
    const void* em = d_in[8];
    float* O = (float*)d_out;

    prep_all<<<BIAS_BLKS + QKV_BLKS, 256>>>(Q, K, V, b0, b1, b2, b3, im, em);

    cudaFuncSetAttribute(attn_mma, cudaFuncAttributeMaxDynamicSharedMemorySize, SMEM_TOTAL);
    dim3 grid(49, NB);
    attn_mma<<<grid, NTH, SMEM_TOTAL>>>(O);

    const int ctotal = NB * (NN - SPLIT_ROW0) * (ND / 4);
    combine_split<<<(ctotal + 255) / 256, 256>>>((float4*)O);
}

// round 16
// speedup vs baseline: 1.0273x; 1.0070x over previous
#include <cuda_runtime.h>
#include <cuda_fp16.h>
#include <math.h>
#include <cstdint>

#define NB 16
#define NN 2048
#define ND 128
#define NTH 128
#define LOG2E 1.4426950408889634f
#define QSCALE (0.08838834764831843f * 1.4426950408889634f)   // 1/sqrt(D) * log2(e)
#define ESHIFT 3.0f
#define SPLIT_ROW0 960          // rows >= this (qt >= 15) are 2-way split-K

// ---------------- device scratch ----------------
__device__ float g_bias[(size_t)NN * NN];   // (sum of biases)*log2e - ESHIFT*log2e
__device__ unsigned char g_qm[NB * NN];     // normalized embeddings_mask
__device__ __align__(16) __half g_kh[(size_t)NB * NN * ND];
__device__ __align__(16) __half g_vh[(size_t)NB * NN * ND];
__device__ __align__(16) float g_p0[(size_t)NB * NN * ND];   // split-K partial O, part 0
__device__ __align__(16) float g_p1[(size_t)NB * NN * ND];   // part 1
__device__ float g_l0[NB * NN];
__device__ float g_l1[NB * NN];

// ---------------- smem layout (bytes) ----------------
#define KV_STAGE 32768
#define T_KH 0
#define T_VH 16384
#define SMEM_TOTAL 65536

// ---------------- PTX helpers ----------------
__device__ __forceinline__ uint32_t smem_u32(const void* p) {
    uint32_t a;
    asm("{ .reg .u64 t; cvta.to.shared.u64 t, %1; cvt.u32.u64 %0, t; }" : "=r"(a) : "l"(p));
    return a;
}
__device__ __forceinline__ void cpa16(uint32_t dst, const void* src) {
    asm volatile("cp.async.cg.shared.global [%0], [%1], 16;" :: "r"(dst), "l"(src));
}
#define CP_COMMIT() asm volatile("cp.async.commit_group;" ::: "memory")
#define CP_WAIT0()  asm volatile("cp.async.wait_group 0;" ::: "memory")

__device__ __forceinline__ void ldsm4(uint32_t& r0, uint32_t& r1, uint32_t& r2, uint32_t& r3,
                                      uint32_t addr) {
    asm volatile("ldmatrix.sync.aligned.m8n8.x4.shared.b16 {%0,%1,%2,%3}, [%4];"
                 : "=r"(r0), "=r"(r1), "=r"(r2), "=r"(r3) : "r"(addr));
}
__device__ __forceinline__ void ldsm4t(uint32_t& r0, uint32_t& r1, uint32_t& r2, uint32_t& r3,
                                       uint32_t addr) {
    asm volatile("ldmatrix.sync.aligned.m8n8.x4.trans.shared.b16 {%0,%1,%2,%3}, [%4];"
                 : "=r"(r0), "=r"(r1), "=r"(r2), "=r"(r3) : "r"(addr));
}
__device__ __forceinline__ void mma_f16(float* d, const uint32_t* a, uint32_t b0, uint32_t b1) {
    asm volatile(
        "mma.sync.aligned.m16n8k16.row.col.f32.f16.f16.f32 "
        "{%0,%1,%2,%3}, {%4,%5,%6,%7}, {%8,%9}, {%0,%1,%2,%3};"
        : "+f"(d[0]), "+f"(d[1]), "+f"(d[2]), "+f"(d[3])
        : "r"(a[0]), "r"(a[1]), "r"(a[2]), "r"(a[3]), "r"(b0), "r"(b1));
}
__device__ __forceinline__ uint32_t h2u(__half2 h) { return *(uint32_t*)&h; }
__device__ __forceinline__ float ex2f(float x) {
    float y; asm("ex2.approx.ftz.f32 %0, %1;" : "=f"(y) : "f"(x)); return y;
}

// ---------------- fused prep kernel: every block runs all phases (balanced) ----------------
#define PREP_BLKS 2048
#define PREP_THR  256

__global__ void prep_all(const float4* __restrict__ K, const float4* __restrict__ V,
                         const float4* __restrict__ ba, const float4* __restrict__ bb,
                         const float4* __restrict__ bc, const float4* __restrict__ bd,
                         const void* __restrict__ im_raw, const void* __restrict__ em_raw) {
    __shared__ int mode_i, mode_e;
    if (threadIdx.x == 0) {
        const unsigned int* wi = (const unsigned int*)im_raw;
        const unsigned int* we = (const unsigned int*)em_raw;
        int mi = 0, me = 0;
        for (int k = 0; k < 64; k++) {
            unsigned int a = wi[k], b = we[k];
            if (a == 0x3F800000u) mi = 2; else if (mi != 2 && a > 1u) mi = 1;
            if (b == 0x3F800000u) me = 2; else if (me != 2 && b > 1u) me = 1;
        }
        mode_i = mi; mode_e = me;
    }
    __syncthreads();
    const int mi = mode_i, me = mode_e;
    const int gstride = PREP_BLKS * PREP_THR;
    const int gtid = blockIdx.x * PREP_THR + threadIdx.x;

    // ---- phase 1: normalize embeddings_mask (used by attn for Q) ----
    for (int i = gtid; i < NB * NN; i += gstride) {
        unsigned char qm;
        if (me == 1)      qm = (((const unsigned char*)em_raw)[i] != 0);
        else if (me == 2) qm = (((const float*)em_raw)[i] != 0.0f);
        else              qm = (((const int*)em_raw)[i] != 0);
        g_qm[i] = qm;
    }

    // ---- phase 2: bias sum (log2 domain, shift folded) ----
    {
        const int n4 = (NN * NN) / 4;
        float4* out = (float4*)g_bias;
        const float sh = ESHIFT * LOG2E;
        for (int i = gtid; i < n4; i += gstride) {
            float4 x = ba[i], y = bb[i], z = bc[i], w = bd[i];
            float4 r;
            r.x = (x.x + y.x + z.x + w.x) * LOG2E - sh;
            r.y = (x.y + y.y + z.y + w.y) * LOG2E - sh;
            r.z = (x.z + y.z + z.z + w.z) * LOG2E - sh;
            r.w = (x.w + y.w + z.w + w.w) * LOG2E - sh;
            out[i] = r;
        }
    }

    // ---- phase 3: K/V masked fp16 conversion ----
    {
        const int n4 = NB * NN * ND / 4;
        uint2* kh = (uint2*)g_kh;
        uint2* vh = (uint2*)g_vh;
        for (int i = gtid; i < n4; i += gstride) {
            const int bn = i >> 5;
            bool kb;
            if (mi == 1)      kb = (((const unsigned char*)im_raw)[bn] != 0);
            else if (mi == 2) kb = (((const float*)im_raw)[bn] != 0.0f);
            else              kb = (((const int*)im_raw)[bn] != 0);
            const float kmf = kb ? 1.0f : 0.0f;

            float4 k = K[i];
            __half2 kh01 = __floats2half2_rn(k.x * kmf, k.y * kmf);
            __half2 kh23 = __floats2half2_rn(k.z * kmf, k.w * kmf);
            kh[i] = make_uint2(h2u(kh01), h2u(kh23));

            float4 v = V[i];
            __half2 vh01 = __floats2half2_rn(v.x * kmf, v.y * kmf);
            __half2 vh23 = __floats2half2_rn(v.z * kmf, v.w * kmf);
            vh[i] = make_uint2(h2u(vh01), h2u(vh23));
        }
    }
}

// ---------------- combine kernel: O = (P0 + P1) / (l0 + l1) for split rows ----------------
__global__ void combine_split(float4* __restrict__ O) {
    const int total = NB * (NN - SPLIT_ROW0) * (ND / 4);
    int idx = blockIdx.x * blockDim.x + threadIdx.x;
    if (idx >= total) return;
    const int d4 = idx & 31;                       // ND/4 = 32
    const int rowc = (idx >> 5) % (NN - SPLIT_ROW0);
    const int b = idx / (32 * (NN - SPLIT_ROW0));
    const int row = SPLIT_ROW0 + rowc;
    const size_t off = ((size_t)b * NN + row) * (ND / 4) + d4;
    float4 a = ((const float4*)g_p0)[off];
    float4 c = ((const float4*)g_p1)[off];
    const float inv = 1.0f / (g_l0[b * NN + row] + g_l1[b * NN + row]);
    float4 o;
    o.x = (a.x + c.x) * inv;
    o.y = (a.y + c.y) * inv;
    o.z = (a.z + c.z) * inv;
    o.w = (a.w + c.w) * inv;
    O[off] = o;
}

// ---------------- KV stage loader: Kh|Vh, 64 rows x 256B each, swizzled ----------------
__device__ __forceinline__ void load_kv(uint32_t stage_base, int b, int k0, int tid) {
    const size_t gbyte = ((size_t)b * NN + k0) * ND * 2;
    const char* sk_h = (const char*)g_kh + gbyte;
    const char* sv_h = (const char*)g_vh + gbyte;
#pragma unroll
    for (int j = 0; j < 8; j++) {
        int idx = tid + NTH * j;
        int row = idx >> 4, c = idx & 15;
        uint32_t d = row * 256 + ((c ^ (row & 7)) << 4);
        uint32_t s = row * 256 + c * 16;
        cpa16(stage_base + T_KH + d, sk_h + s);
        cpa16(stage_base + T_VH + d, sv_h + s);
    }
}

// ---------------- FA2-style kernel, 2-way split-K, Q loaded fp32 in-kernel ----------------
__global__ __launch_bounds__(NTH, 3)
void attn_mma(const float* __restrict__ Qg, float* __restrict__ Og) {
    extern __shared__ char smc[];
    const uint32_t base = smem_u32(smc);
    const int tid = threadIdx.x;
    const int lane = tid & 31, wid = tid >> 5;
    const int g = lane >> 2, r = lane & 3;
    const int lane7 = lane & 7, laneHi = lane >> 4, lane8 = (lane >> 3) & 1;
    const int b = blockIdx.y;

    // ---- piece decode: x<34 -> split halves of qt 31..15 (big first); else single ----
    const int x = blockIdx.x;
    int qt, kt0, kt1, part, split;
    if (x < 34) {
        qt = 31 - (x >> 1);
        part = x & 1;
        split = 1;
        const int nk = qt + 1, h = (nk + 1) >> 1;
        kt0 = part ? h : 0;
        kt1 = part ? nk : h;
    } else {
        qt = 48 - x;
        part = 0;
        split = 0;
        kt0 = 0;
        kt1 = qt + 1;
    }
    const int q0 = qt * 64;
    const int row0g = q0 + 16 * wid + g;

    // ---- prologue: KV stage kt0 via cp.async; Q fragments direct from fp32 global ----
    load_kv(base + (uint32_t)(kt0 & 1) * KV_STAGE, b, kt0 * 64, tid);
    CP_COMMIT();

    uint32_t qf[8][4];
    {
        const float qmfa = g_qm[b * NN + row0g]     ? QSCALE : 0.0f;
        const float qmfb = g_qm[b * NN + row0g + 8] ? QSCALE : 0.0f;
        const float* qa = Qg + ((size_t)b * NN + row0g) * ND + 2 * r;
        const float* qb = qa + 8 * ND;
#pragma unroll
        for (int ks = 0; ks < 8; ks++) {
            float2 xa0 = __ldg((const float2*)(qa + 16 * ks));
            float2 xb0 = __ldg((const float2*)(qb + 16 * ks));
            float2 xa1 = __ldg((const float2*)(qa + 16 * ks + 8));
            float2 xb1 = __ldg((const float2*)(qb + 16 * ks + 8));
            qf[ks][0] = h2u(__floats2half2_rn(xa0.x * qmfa, xa0.y * qmfa));
            qf[ks][1] = h2u(__floats2half2_rn(xb0.x * qmfb, xb0.y * qmfb));
            qf[ks][2] = h2u(__floats2half2_rn(xa1.x * qmfa, xa1.y * qmfa));
            qf[ks][3] = h2u(__floats2half2_rn(xb1.x * qmfb, xb1.y * qmfb));
        }
    }
    CP_WAIT0();
    __syncthreads();

    // ---- per-lane address precompute ----
    uint32_t krowb[4];
#pragma unroll
    for (int t = 0; t < 4; t++)
        krowb[t] = (uint32_t)(16 * t + 8 * laneHi + lane7) * 256;
    const uint32_t vrow256 = (uint32_t)(lane7 + 8 * lane8) * 256;
    uint32_t cvx[8];
#pragma unroll
    for (int p = 0; p < 8; p++)
        cvx[p] = (uint32_t)(((2 * p + laneHi) ^ lane7) << 4);

    const char* bp = (const char*)g_bias +
                     (((size_t)row0g * NN) + 2 * r + (size_t)kt0 * 64) * 4;

    float o_acc[16][4];
#pragma unroll
    for (int dt = 0; dt < 16; dt++)
#pragma unroll
        for (int i = 0; i < 4; i++) o_acc[dt][i] = 0.0f;
    float lsum0 = 0.0f, lsum1 = 0.0f;

    for (int kt = kt0; kt < kt1; kt++) {
        const int k0 = kt * 64;
        const uint32_t kvb = base + (uint32_t)(kt & 1) * KV_STAGE;

        // ---- distance-1 prefetch (src L2-resident) ----
        if (kt + 1 < kt1) {
            load_kv(base + (uint32_t)((kt + 1) & 1) * KV_STAGE, b, k0 + 64, tid);
            CP_COMMIT();
        }

        // ---- bias: local offsets only (bp carries the k0 advance) ----
        float2 bias2[8][2];
#pragma unroll
        for (int nt = 0; nt < 8; nt++) {
#pragma unroll
            for (int h = 0; h < 2; h++)
                bias2[nt][h] = __ldg((const float2*)(bp +
                    ((size_t)(8 * h) * NN + (size_t)(8 * nt)) * 4));
        }

        // ---- QK: S(16x64) = Q(16x128) x K^T; K streamed per-t ----
        float s[8][4];
#pragma unroll
        for (int nt = 0; nt < 8; nt++)
#pragma unroll
            for (int i = 0; i < 4; i++) s[nt][i] = 0.0f;

#pragma unroll
        for (int ks = 0; ks < 8; ks++) {
            const uint32_t koff = (uint32_t)(((lane8 + 2 * ks) ^ lane7) << 4);
#pragma unroll
            for (int t = 0; t < 4; t++) {
                uint32_t k0r, k1r, k2r, k3r;
                ldsm4(k0r, k1r, k2r, k3r, kvb + T_KH + krowb[t] + koff);
                mma_f16(s[2 * t],     qf[ks], k0r, k1r);
                mma_f16(s[2 * t + 1], qf[ks], k2r, k3r);
            }
        }

        // ---- chunked softmax + PV ----
        const bool safe = (k0 + 63 <= q0);
#pragma unroll
        for (int c = 0; c < 4; c++) {
            uint32_t pf[4];
#pragma unroll
            for (int j = 0; j < 2; j++) {
                const int nt = 2 * c + j;
                float p0 = ex2f(s[nt][0] + bias2[nt][0].x);
                float p1 = ex2f(s[nt][1] + bias2[nt][0].y);
                float p2 = ex2f(s[nt][2] + bias2[nt][1].x);
                float p3 = ex2f(s[nt][3] + bias2[nt][1].y);
                if (!safe) {
                    const int colg = k0 + 8 * nt + 2 * r;
                    p0 = (colg     <= row0g)     ? p0 : 0.0f;
                    p1 = (colg + 1 <= row0g)     ? p1 : 0.0f;
                    p2 = (colg     <= row0g + 8) ? p2 : 0.0f;
                    p3 = (colg + 1 <= row0g + 8) ? p3 : 0.0f;
                }
                lsum0 += p0 + p1;
                lsum1 += p2 + p3;
                pf[2 * j]     = h2u(__floats2half2_rn(p0, p1));
                pf[2 * j + 1] = h2u(__floats2half2_rn(p2, p3));
            }
            const uint32_t vbase = kvb + T_VH + vrow256 + (uint32_t)c * 4096;
#pragma unroll
            for (int p = 0; p < 8; p++) {
                uint32_t v0, v1, v2, v3;
                ldsm4t(v0, v1, v2, v3, vbase + cvx[p]);
                mma_f16(o_acc[2 * p],     pf, v0, v1);
                mma_f16(o_acc[2 * p + 1], pf, v2, v3);
            }
        }

        if (kt + 1 < kt1) {
            CP_WAIT0();
            __syncthreads();
        }
        bp += 256;
    }

    // ---- epilogue ----
    lsum0 += __shfl_xor_sync(0xffffffffu, lsum0, 1);
    lsum0 += __shfl_xor_sync(0xffffffffu, lsum0, 2);
    lsum1 += __shfl_xor_sync(0xffffffffu, lsum1, 1);
    lsum1 += __shfl_xor_sync(0xffffffffu, lsum1, 2);

    if (!split) {
        const float inv0 = 1.0f / lsum0;
        const float inv1 = 1.0f / lsum1;
        float* dst0 = Og + ((size_t)b * NN + row0g) * ND;
        float* dst1 = dst0 + 8 * ND;
#pragma unroll
        for (int dt = 0; dt < 16; dt++) {
            float2 v0, v1;
            v0.x = o_acc[dt][0] * inv0;
            v0.y = o_acc[dt][1] * inv0;
            v1.x = o_acc[dt][2] * inv1;
            v1.y = o_acc[dt][3] * inv1;
            *(float2*)(dst0 + 8 * dt + 2 * r) = v0;
            *(float2*)(dst1 + 8 * dt + 2 * r) = v1;
        }
    } else {
        float* gp = part ? g_p1 : g_p0;
        float* gl = part ? g_l1 : g_l0;
        float* dst0 = gp + ((size_t)b * NN + row0g) * ND;
        float* dst1 = dst0 + 8 * ND;
#pragma unroll
        for (int dt = 0; dt < 16; dt++) {
            *(float2*)(dst0 + 8 * dt + 2 * r) = make_float2(o_acc[dt][0], o_acc[dt][1]);
            *(float2*)(dst1 + 8 * dt + 2 * r) = make_float2(o_acc[dt][2], o_acc[dt][3]);
        }
        if (r == 0) {
            gl[b * NN + row0g] = lsum0;
            gl[b * NN + row0g + 8] = lsum1;
        }
    }
}

// ---------------- launch ----------------
extern "C" void kernel_launch(void* const* d_in, const int* in_sizes, int n_in,
                              void* d_out, int out_size) {
    const float* Q   = (const float*)d_in[0];
    const float4* K  = (const float4*)d_in[1];
    const float4* V  = (const float4*)d_in[2];
    const float4* b0 = (const float4*)d_in[3];
    const float4* b1 = (const float4*)d_in[4];
    const float4* b2 = (const float4*)d_in[5];
    const float4* b3 = (const float4*)d_in[6];
    const void* im = d_in[7];
    const void* em = d_in[8];
    float* O = (float*)d_out;

    prep_all<<<PREP_BLKS, PREP_THR>>>(K, V, b0, b1, b2, b3, im, em);

    cudaFuncSetAttribute(attn_mma, cudaFuncAttributeMaxDynamicSharedMemorySize, SMEM_TOTAL);
    dim3 grid(49, NB);
    attn_mma<<<grid, NTH, SMEM_TOTAL>>>(Q, O);

    const int ctotal = NB * (NN - SPLIT_ROW0) * (ND / 4);
    combine_split<<<(ctotal + 255) / 256, 256>>>((float4*)O);
}

// round 17
// speedup vs baseline: 1.0783x; 1.0497x over previous
#include <cuda_runtime.h>
#include <cuda_fp16.h>
#include <math.h>
#include <cstdint>

#define NB 16
#define NN 2048
#define ND 128
#define NTH 128
#define LOG2E 1.4426950408889634f
#define QSCALE (0.08838834764831843f * 1.4426950408889634f)   // 1/sqrt(D) * log2(e)
#define SPLIT_ROW0 960          // rows >= this (qt >= 15) are 2-way split-K

// ---------------- device scratch ----------------
__device__ __align__(16) __half g_biash[(size_t)NN * NN];   // (sum of biases)*log2e, fp16
__device__ unsigned char g_qm[NB * NN];
__device__ __align__(16) __half g_kh[(size_t)NB * NN * ND];
__device__ __align__(16) __half g_vh[(size_t)NB * NN * ND];
__device__ __align__(16) float g_p0[(size_t)NB * NN * ND];
__device__ __align__(16) float g_p1[(size_t)NB * NN * ND];
__device__ float g_l0[NB * NN];
__device__ float g_l1[NB * NN];

// ---------------- smem layout (bytes) ----------------
#define KV_STAGE 32768
#define T_KH 0
#define T_VH 16384
#define SMEM_TOTAL 65536

// ---------------- PTX helpers ----------------
__device__ __forceinline__ uint32_t smem_u32(const void* p) {
    uint32_t a;
    asm("{ .reg .u64 t; cvta.to.shared.u64 t, %1; cvt.u32.u64 %0, t; }" : "=r"(a) : "l"(p));
    return a;
}
__device__ __forceinline__ void cpa16(uint32_t dst, const void* src) {
    asm volatile("cp.async.cg.shared.global [%0], [%1], 16;" :: "r"(dst), "l"(src));
}
#define CP_COMMIT() asm volatile("cp.async.commit_group;" ::: "memory")
#define CP_WAIT0()  asm volatile("cp.async.wait_group 0;" ::: "memory")

__device__ __forceinline__ void ldsm4(uint32_t& r0, uint32_t& r1, uint32_t& r2, uint32_t& r3,
                                      uint32_t addr) {
    asm volatile("ldmatrix.sync.aligned.m8n8.x4.shared.b16 {%0,%1,%2,%3}, [%4];"
                 : "=r"(r0), "=r"(r1), "=r"(r2), "=r"(r3) : "r"(addr));
}
__device__ __forceinline__ void ldsm4t(uint32_t& r0, uint32_t& r1, uint32_t& r2, uint32_t& r3,
                                       uint32_t addr) {
    asm volatile("ldmatrix.sync.aligned.m8n8.x4.trans.shared.b16 {%0,%1,%2,%3}, [%4];"
                 : "=r"(r0), "=r"(r1), "=r"(r2), "=r"(r3) : "r"(addr));
}
__device__ __forceinline__ void mma_f16(float* d, const uint32_t* a, uint32_t b0, uint32_t b1) {
    asm volatile(
        "mma.sync.aligned.m16n8k16.row.col.f32.f16.f16.f32 "
        "{%0,%1,%2,%3}, {%4,%5,%6,%7}, {%8,%9}, {%0,%1,%2,%3};"
        : "+f"(d[0]), "+f"(d[1]), "+f"(d[2]), "+f"(d[3])
        : "r"(a[0]), "r"(a[1]), "r"(a[2]), "r"(a[3]), "r"(b0), "r"(b1));
}
__device__ __forceinline__ uint32_t h2u(__half2 h) { return *(uint32_t*)&h; }
__device__ __forceinline__ float ex2f(float x) {
    float y; asm("ex2.approx.ftz.f32 %0, %1;" : "=f"(y) : "f"(x)); return y;
}

// ---------------- fused prep kernel: balanced, 2 elements/thread straight-line ----------------
#define PREP_BLKS 2048
#define PREP_THR  256
#define GSTRIDE (PREP_BLKS * PREP_THR)   // 524288

__global__ void prep_all(const float4* __restrict__ K, const float4* __restrict__ V,
                         const float4* __restrict__ ba, const float4* __restrict__ bb,
                         const float4* __restrict__ bc, const float4* __restrict__ bd,
                         const void* __restrict__ im_raw, const void* __restrict__ em_raw) {
    __shared__ int mode_i, mode_e;
    if (threadIdx.x == 0) {
        const unsigned int* wi = (const unsigned int*)im_raw;
        const unsigned int* we = (const unsigned int*)em_raw;
        int mi = 0, me = 0;
        for (int k = 0; k < 64; k++) {
            unsigned int a = wi[k], b = we[k];
            if (a == 0x3F800000u) mi = 2; else if (mi != 2 && a > 1u) mi = 1;
            if (b == 0x3F800000u) me = 2; else if (me != 2 && b > 1u) me = 1;
        }
        mode_i = mi; mode_e = me;
    }
    __syncthreads();
    const int mi = mode_i, me = mode_e;
    const int gtid = blockIdx.x * PREP_THR + threadIdx.x;

    // ---- phase 1: normalize embeddings_mask ----
    if (gtid < NB * NN) {
        unsigned char qm;
        if (me == 1)      qm = (((const unsigned char*)em_raw)[gtid] != 0);
        else if (me == 2) qm = (((const float*)em_raw)[gtid] != 0.0f);
        else              qm = (((const int*)em_raw)[gtid] != 0);
        g_qm[gtid] = qm;
    }

    // ---- phase 2: bias sum (log2 domain, fp16, no shift); 2 float4-groups/thread ----
    {
        uint2* out = (uint2*)g_biash;     // 4 halves per uint2
        const int i0 = gtid, i1 = gtid + GSTRIDE;
        float4 x0 = ba[i0], y0 = bb[i0], z0 = bc[i0], w0 = bd[i0];
        float4 x1 = ba[i1], y1 = bb[i1], z1 = bc[i1], w1 = bd[i1];
        __half2 h00 = __floats2half2_rn((x0.x + y0.x + z0.x + w0.x) * LOG2E,
                                        (x0.y + y0.y + z0.y + w0.y) * LOG2E);
        __half2 h01 = __floats2half2_rn((x0.z + y0.z + z0.z + w0.z) * LOG2E,
                                        (x0.w + y0.w + z0.w + w0.w) * LOG2E);
        __half2 h10 = __floats2half2_rn((x1.x + y1.x + z1.x + w1.x) * LOG2E,
                                        (x1.y + y1.y + z1.y + w1.y) * LOG2E);
        __half2 h11 = __floats2half2_rn((x1.z + y1.z + z1.z + w1.z) * LOG2E,
                                        (x1.w + y1.w + z1.w + w1.w) * LOG2E);
        out[i0] = make_uint2(h2u(h00), h2u(h01));
        out[i1] = make_uint2(h2u(h10), h2u(h11));
    }

    // ---- phase 3: K/V masked fp16 conversion; 2 float4-groups/thread ----
    {
        uint2* kh = (uint2*)g_kh;
        uint2* vh = (uint2*)g_vh;
#pragma unroll
        for (int u = 0; u < 2; u++) {
            const int i = gtid + u * GSTRIDE;
            const int bn = i >> 5;
            bool kb;
            if (mi == 1)      kb = (((const unsigned char*)im_raw)[bn] != 0);
            else if (mi == 2) kb = (((const float*)im_raw)[bn] != 0.0f);
            else              kb = (((const int*)im_raw)[bn] != 0);
            const float kmf = kb ? 1.0f : 0.0f;

            float4 k = K[i];
            __half2 kh01 = __floats2half2_rn(k.x * kmf, k.y * kmf);
            __half2 kh23 = __floats2half2_rn(k.z * kmf, k.w * kmf);
            kh[i] = make_uint2(h2u(kh01), h2u(kh23));

            float4 v = V[i];
            __half2 vh01 = __floats2half2_rn(v.x * kmf, v.y * kmf);
            __half2 vh23 = __floats2half2_rn(v.z * kmf, v.w * kmf);
            vh[i] = make_uint2(h2u(vh01), h2u(vh23));
        }
    }
}

// ---------------- combine kernel: O = (P0 + P1) / (l0 + l1) for split rows ----------------
__global__ void combine_split(float4* __restrict__ O) {
    const int total = NB * (NN - SPLIT_ROW0) * (ND / 4);
    int idx = blockIdx.x * blockDim.x + threadIdx.x;
    if (idx >= total) return;
    const int d4 = idx & 31;
    const int rowc = (idx >> 5) % (NN - SPLIT_ROW0);
    const int b = idx / (32 * (NN - SPLIT_ROW0));
    const int row = SPLIT_ROW0 + rowc;
    const size_t off = ((size_t)b * NN + row) * (ND / 4) + d4;
    float4 a = ((const float4*)g_p0)[off];
    float4 c = ((const float4*)g_p1)[off];
    const float inv = 1.0f / (g_l0[b * NN + row] + g_l1[b * NN + row]);
    float4 o;
    o.x = (a.x + c.x) * inv;
    o.y = (a.y + c.y) * inv;
    o.z = (a.z + c.z) * inv;
    o.w = (a.w + c.w) * inv;
    O[off] = o;
}

// ---------------- KV stage loader: Kh|Vh, 64 rows x 256B each, swizzled ----------------
__device__ __forceinline__ void load_kv(uint32_t stage_base, int b, int k0, int tid) {
    const size_t gbyte = ((size_t)b * NN + k0) * ND * 2;
    const char* sk_h = (const char*)g_kh + gbyte;
    const char* sv_h = (const char*)g_vh + gbyte;
#pragma unroll
    for (int j = 0; j < 8; j++) {
        int idx = tid + NTH * j;
        int row = idx >> 4, c = idx & 15;
        uint32_t d = row * 256 + ((c ^ (row & 7)) << 4);
        uint32_t s = row * 256 + c * 16;
        cpa16(stage_base + T_KH + d, sk_h + s);
        cpa16(stage_base + T_VH + d, sv_h + s);
    }
}

// ---------------- FA2-style kernel, 2-way split-K, Q fp32 direct, fp16 bias ----------------
__global__ __launch_bounds__(NTH, 3)
void attn_mma(const float* __restrict__ Qg, float* __restrict__ Og) {
    extern __shared__ char smc[];
    const uint32_t base = smem_u32(smc);
    const int tid = threadIdx.x;
    const int lane = tid & 31, wid = tid >> 5;
    const int g = lane >> 2, r = lane & 3;
    const int lane7 = lane & 7, laneHi = lane >> 4, lane8 = (lane >> 3) & 1;
    const int b = blockIdx.y;

    // ---- piece decode ----
    const int x = blockIdx.x;
    int qt, kt0, kt1, part, split;
    if (x < 34) {
        qt = 31 - (x >> 1);
        part = x & 1;
        split = 1;
        const int nk = qt + 1, h = (nk + 1) >> 1;
        kt0 = part ? h : 0;
        kt1 = part ? nk : h;
    } else {
        qt = 48 - x;
        part = 0;
        split = 0;
        kt0 = 0;
        kt1 = qt + 1;
    }
    const int q0 = qt * 64;
    const int row0g = q0 + 16 * wid + g;

    // ---- prologue: KV stage kt0 via cp.async; Q fragments direct from fp32 global ----
    load_kv(base + (uint32_t)(kt0 & 1) * KV_STAGE, b, kt0 * 64, tid);
    CP_COMMIT();

    uint32_t qf[8][4];
    {
        const float qmfa = g_qm[b * NN + row0g]     ? QSCALE : 0.0f;
        const float qmfb = g_qm[b * NN + row0g + 8] ? QSCALE : 0.0f;
        const float* qa = Qg + ((size_t)b * NN + row0g) * ND + 2 * r;
        const float* qb = qa + 8 * ND;
#pragma unroll
        for (int ks = 0; ks < 8; ks++) {
            float2 xa0 = __ldg((const float2*)(qa + 16 * ks));
            float2 xb0 = __ldg((const float2*)(qb + 16 * ks));
            float2 xa1 = __ldg((const float2*)(qa + 16 * ks + 8));
            float2 xb1 = __ldg((const float2*)(qb + 16 * ks + 8));
            qf[ks][0] = h2u(__floats2half2_rn(xa0.x * qmfa, xa0.y * qmfa));
            qf[ks][1] = h2u(__floats2half2_rn(xb0.x * qmfb, xb0.y * qmfb));
            qf[ks][2] = h2u(__floats2half2_rn(xa1.x * qmfa, xa1.y * qmfa));
            qf[ks][3] = h2u(__floats2half2_rn(xb1.x * qmfb, xb1.y * qmfb));
        }
    }
    CP_WAIT0();
    __syncthreads();

    // ---- per-lane address precompute ----
    uint32_t krowb[4];
#pragma unroll
    for (int t = 0; t < 4; t++)
        krowb[t] = (uint32_t)(16 * t + 8 * laneHi + lane7) * 256;
    const uint32_t vrow256 = (uint32_t)(lane7 + 8 * lane8) * 256;
    uint32_t cvx[8];
#pragma unroll
    for (int p = 0; p < 8; p++)
        cvx[p] = (uint32_t)(((2 * p + laneHi) ^ lane7) << 4);

    const __half* bph = g_biash + ((size_t)row0g * NN) + 2 * r + (size_t)kt0 * 64;

    float o_acc[16][4];
#pragma unroll
    for (int dt = 0; dt < 16; dt++)
#pragma unroll
        for (int i = 0; i < 4; i++) o_acc[dt][i] = 0.0f;
    float lsum0 = 0.0f, lsum1 = 0.0f;

    for (int kt = kt0; kt < kt1; kt++) {
        const int k0 = kt * 64;
        const uint32_t kvb = base + (uint32_t)(kt & 1) * KV_STAGE;

        if (kt + 1 < kt1) {
            load_kv(base + (uint32_t)((kt + 1) & 1) * KV_STAGE, b, k0 + 64, tid);
            CP_COMMIT();
        }

        // ---- bias: fp16 pairs, one uint32 per (nt, h) ----
        float2 bias2[8][2];
#pragma unroll
        for (int nt = 0; nt < 8; nt++) {
#pragma unroll
            for (int h = 0; h < 2; h++) {
                uint32_t bv = __ldg((const uint32_t*)(bph + (size_t)(8 * h) * NN + 8 * nt));
                bias2[nt][h] = __half22float2(*(const __half2*)&bv);
            }
        }

        // ---- QK: S(16x64) = Q(16x128) x K^T; K streamed per-t ----
        float s[8][4];
#pragma unroll
        for (int nt = 0; nt < 8; nt++)
#pragma unroll
            for (int i = 0; i < 4; i++) s[nt][i] = 0.0f;

#pragma unroll
        for (int ks = 0; ks < 8; ks++) {
            const uint32_t koff = (uint32_t)(((lane8 + 2 * ks) ^ lane7) << 4);
#pragma unroll
            for (int t = 0; t < 4; t++) {
                uint32_t k0r, k1r, k2r, k3r;
                ldsm4(k0r, k1r, k2r, k3r, kvb + T_KH + krowb[t] + koff);
                mma_f16(s[2 * t],     qf[ks], k0r, k1r);
                mma_f16(s[2 * t + 1], qf[ks], k2r, k3r);
            }
        }

        // ---- chunked softmax + PV (no shift: scores bounded, fp16-P safe) ----
        const bool safe = (k0 + 63 <= q0);
#pragma unroll
        for (int c = 0; c < 4; c++) {
            uint32_t pf[4];
#pragma unroll
            for (int j = 0; j < 2; j++) {
                const int nt = 2 * c + j;
                float p0 = ex2f(s[nt][0] + bias2[nt][0].x);
                float p1 = ex2f(s[nt][1] + bias2[nt][0].y);
                float p2 = ex2f(s[nt][2] + bias2[nt][1].x);
                float p3 = ex2f(s[nt][3] + bias2[nt][1].y);
                if (!safe) {
                    const int colg = k0 + 8 * nt + 2 * r;
                    p0 = (colg     <= row0g)     ? p0 : 0.0f;
                    p1 = (colg + 1 <= row0g)     ? p1 : 0.0f;
                    p2 = (colg     <= row0g + 8) ? p2 : 0.0f;
                    p3 = (colg + 1 <= row0g + 8) ? p3 : 0.0f;
                }
                lsum0 += p0 + p1;
                lsum1 += p2 + p3;
                pf[2 * j]     = h2u(__floats2half2_rn(p0, p1));
                pf[2 * j + 1] = h2u(__floats2half2_rn(p2, p3));
            }
            const uint32_t vbase = kvb + T_VH + vrow256 + (uint32_t)c * 4096;
#pragma unroll
            for (int p = 0; p < 8; p++) {
                uint32_t v0, v1, v2, v3;
                ldsm4t(v0, v1, v2, v3, vbase + cvx[p]);
                mma_f16(o_acc[2 * p],     pf, v0, v1);
                mma_f16(o_acc[2 * p + 1], pf, v2, v3);
            }
        }

        if (kt + 1 < kt1) {
            CP_WAIT0();
            __syncthreads();
        }
        bph += 64;
    }

    // ---- epilogue ----
    lsum0 += __shfl_xor_sync(0xffffffffu, lsum0, 1);
    lsum0 += __shfl_xor_sync(0xffffffffu, lsum0, 2);
    lsum1 += __shfl_xor_sync(0xffffffffu, lsum1, 1);
    lsum1 += __shfl_xor_sync(0xffffffffu, lsum1, 2);

    if (!split) {
        const float inv0 = 1.0f / lsum0;
        const float inv1 = 1.0f / lsum1;
        float* dst0 = Og + ((size_t)b * NN + row0g) * ND;
        float* dst1 = dst0 + 8 * ND;
#pragma unroll
        for (int dt = 0; dt < 16; dt++) {
            float2 v0, v1;
            v0.x = o_acc[dt][0] * inv0;
            v0.y = o_acc[dt][1] * inv0;
            v1.x = o_acc[dt][2] * inv1;
            v1.y = o_acc[dt][3] * inv1;
            *(float2*)(dst0 + 8 * dt + 2 * r) = v0;
            *(float2*)(dst1 + 8 * dt + 2 * r) = v1;
        }
    } else {
        float* gp = part ? g_p1 : g_p0;
        float* gl = part ? g_l1 : g_l0;
        float* dst0 = gp + ((size_t)b * NN + row0g) * ND;
        float* dst1 = dst0 + 8 * ND;
#pragma unroll
        for (int dt = 0; dt < 16; dt++) {
            *(float2*)(dst0 + 8 * dt + 2 * r) = make_float2(o_acc[dt][0], o_acc[dt][1]);
            *(float2*)(dst1 + 8 * dt + 2 * r) = make_float2(o_acc[dt][2], o_acc[dt][3]);
        }
        if (r == 0) {
            gl[b * NN + row0g] = lsum0;
            gl[b * NN + row0g + 8] = lsum1;
        }
    }
}

// ---------------- launch ----------------
extern "C" void kernel_launch(void* const* d_in, const int* in_sizes, int n_in,
                              void* d_out, int out_size) {
    const float* Q   = (const float*)d_in[0];
    const float4* K  = (const float4*)d_in[1];
    const float4* V  = (const float4*)d_in[2];
    const float4* b0 = (const float4*)d_in[3];
    const float4* b1 = (const float4*)d_in[4];
    const float4* b2 = (const float4*)d_in[5];
    const float4* b3 = (const float4*)d_in[6];
    const void* im = d_in[7];
    const void* em = d_in[8];
    float* O = (float*)d_out;

    prep_all<<<PREP_BLKS, PREP_THR>>>(K, V, b0, b1, b2, b3, im, em);

    cudaFuncSetAttribute(attn_mma, cudaFuncAttributeMaxDynamicSharedMemorySize, SMEM_TOTAL);
    dim3 grid(49, NB);
    attn_mma<<<grid, NTH, SMEM_TOTAL>>>(Q, O);

    const int ctotal = NB * (NN - SPLIT_ROW0) * (ND / 4);
    combine_split<<<(ctotal + 255) / 256, 256>>>((float4*)O);
}